// round 1
// baseline (speedup 1.0000x reference)
#include <cuda_runtime.h>

// GeodesicLayer: y[n,o] = max_t sum_{b,i} h[n,b,i] * W[(b+5t)%80][i][o]
// h[n,b,i] = sum_k conn_val[n*80+b,k] * x[conn_idx[n*80+b,k], i]
//
// Constants from the reference:
#define NVERT   30000
#define BBINS   80
#define INCH    16
#define OUTCH   32
#define TBINS   16
#define PBINS   5
#define KNNZ    3

#define VT        8      // vertices per block
#define NTHREADS  256
#define HS_STRIDE 8      // h_s row stride in floats (transposed layout [1280][8])

#define W_S_FLOATS   (BBINS * INCH * OUTCH)        // 40960
#define H_S_FLOATS   (BBINS * INCH * HS_STRIDE)    // 10240
#define SMEM_BYTES   ((W_S_FLOATS + H_S_FLOATS) * 4)  // 204800

typedef unsigned long long u64;

__device__ __forceinline__ u64 dup2(float f) {
    u64 r;
    asm("mov.b64 %0, {%1, %1};" : "=l"(r) : "f"(f));
    return r;
}
__device__ __forceinline__ void fma2(u64& d, u64 a, u64 b) {
    // packed 2x fp32 FMA (Blackwell FFMA2)
    asm("fma.rn.f32x2 %0, %1, %2, %0;" : "+l"(d) : "l"(a), "l"(b));
}

__global__ __launch_bounds__(NTHREADS, 1)
void geodesic_fused_kernel(const float* __restrict__ x,
                           const int*   __restrict__ cidx,
                           const float* __restrict__ cval,
                           const float* __restrict__ wts,
                           float*       __restrict__ out)
{
    extern __shared__ float smem[];
    float* W_s = smem;                   // [80][16][32] fp32 = 160 KB
    float* h_s = smem + W_S_FLOATS;      // [1280][8] fp32 (transposed) = 40 KB

    const int tid   = threadIdx.x;
    const int vbase = blockIdx.x * VT;

    // ---- stage all weights into SMEM (coalesced float4 copy) ----
    {
        const float4* src = (const float4*)wts;
        float4*       dst = (float4*)W_s;
        #pragma unroll
        for (int j = 0; j < W_S_FLOATS / 4 / NTHREADS; ++j)   // 40 iters
            dst[tid + j * NTHREADS] = src[tid + j * NTHREADS];
    }

    // ---- gather: build h tile for 8 verts x 80 bins x 16 ch ----
    // 16 threads per conn row: lane c = channel. x row loads are 64B coalesced.
    {
        const int c  = tid & 15;
        const int rg = tid >> 4;        // 0..15 row slot
        #pragma unroll 4
        for (int r0 = 0; r0 < VT * BBINS; r0 += 16) {
            int r = r0 + rg;            // local row 0..639
            int v = r / BBINS;
            int b = r - v * BBINS;
            int grow = (vbase + v) * BBINS + b;      // < 2.4M, fits int
            const int*   ip = cidx + grow * KNNZ;
            const float* vp = cval + grow * KNNZ;
            int   i0 = ip[0], i1 = ip[1], i2 = ip[2];
            float a0 = vp[0], a1 = vp[1], a2 = vp[2];
            float acc = a0 * x[i0 * INCH + c]
                      + a1 * x[i1 * INCH + c]
                      + a2 * x[i2 * INCH + c];
            h_s[(b * INCH + c) * HS_STRIDE + v] = acc;
        }
    }
    __syncthreads();

    // ---- GEMM: thread owns (4 verts, 4 outs, one t) ----
    const int vg = tid >> 7;            // vert group: verts 4*vg .. 4*vg+3
    const int rr = tid & 127;
    const int t  = rr >> 3;             // 0..15
    const int o  = (rr & 7) << 2;       // 0,4,...,28

    u64 acc[2][4];
    #pragma unroll
    for (int a = 0; a < 2; ++a)
        #pragma unroll
        for (int c2 = 0; c2 < 4; ++c2) acc[a][c2] = 0ull;

    int wbin = PBINS * t;               // (b + 5t) % 80, maintained incrementally
    const float* hbase = h_s + vg * 4;

    #pragma unroll 1
    for (int b = 0; b < BBINS; ++b) {
        const float* wp = W_s + wbin * (INCH * OUTCH) + o;
        const float* hp = hbase + b * (INCH * HS_STRIDE);
        #pragma unroll
        for (int i = 0; i < INCH; ++i) {
            // h pair loads: 16B broadcast LDS (same addr for whole warp)
            const ulonglong2 hv = *(const ulonglong2*)(hp + i * HS_STRIDE);
            // weights: 16B per lane, 128B contiguous per t-group -> conflict-free
            const float4 w4 = *(const float4*)(wp + i * OUTCH);
            u64 w0 = dup2(w4.x), w1 = dup2(w4.y), w2 = dup2(w4.z), w3 = dup2(w4.w);
            fma2(acc[0][0], hv.x, w0);
            fma2(acc[0][1], hv.x, w1);
            fma2(acc[0][2], hv.x, w2);
            fma2(acc[0][3], hv.x, w3);
            fma2(acc[1][0], hv.y, w0);
            fma2(acc[1][1], hv.y, w1);
            fma2(acc[1][2], hv.y, w2);
            fma2(acc[1][3], hv.y, w3);
        }
        ++wbin;
        if (wbin == BBINS) wbin = 0;
    }
    __syncthreads();   // everyone done reading h_s before reuse as tmp

    // ---- stage partials tmp[t][vert][o] (reuse h_s region, 16 KB) ----
    float* tmp = h_s;
    #pragma unroll
    for (int vp2 = 0; vp2 < 2; ++vp2) {
        #pragma unroll
        for (int c2 = 0; c2 < 4; ++c2) {
            float lo, hi;
            asm("mov.b64 {%0, %1}, %2;" : "=f"(lo), "=f"(hi) : "l"(acc[vp2][c2]));
            int vlo = vg * 4 + vp2 * 2;
            tmp[(t * VT + vlo    ) * OUTCH + o + c2] = lo;
            tmp[(t * VT + vlo + 1) * OUTCH + o + c2] = hi;
        }
    }
    __syncthreads();

    // ---- max over t, one output per thread (coalesced STG) ----
    {
        int v  = tid >> 5;      // 0..7
        int oo = tid & 31;      // 0..31
        float m = tmp[(0 * VT + v) * OUTCH + oo];
        #pragma unroll
        for (int tt = 1; tt < TBINS; ++tt)
            m = fmaxf(m, tmp[(tt * VT + v) * OUTCH + oo]);
        out[(vbase + v) * OUTCH + oo] = m;
    }
}

extern "C" void kernel_launch(void* const* d_in, const int* in_sizes, int n_in,
                              void* d_out, int out_size)
{
    // metadata order: x (480000 f32), conn_idx (7.2M i32), conn_val (7.2M f32),
    // weights (40960 f32). out: 30000*32 f32.
    const float* x    = (const float*)d_in[0];
    const int*   cidx = (const int*)  d_in[1];
    const float* cval = (const float*)d_in[2];
    const float* wts  = (const float*)d_in[3];
    float* out = (float*)d_out;

    cudaFuncSetAttribute(geodesic_fused_kernel,
                         cudaFuncAttributeMaxDynamicSharedMemorySize, SMEM_BYTES);

    geodesic_fused_kernel<<<NVERT / VT, NTHREADS, SMEM_BYTES>>>(x, cidx, cval, wts, out);
}

// round 2
// speedup vs baseline: 1.0533x; 1.0533x over previous
#include <cuda_runtime.h>

// GeodesicLayer: y[n,o] = max_t sum_{b,i} h[n,b,i] * W[(b+5t)%80][i][o]
// h[n,b,i] = sum_k conn_val[n*80+b,k] * x[conn_idx[n*80+b,k], i]
//
// Constants from the reference:
#define NVERT   30000
#define BBINS   80
#define INCH    16
#define OUTCH   32
#define TBINS   16
#define PBINS   5
#define KNNZ    3

#define VT        8      // vertices per block
#define NTHREADS  256
#define HS_STRIDE 8      // h_s row stride in floats (transposed layout [1280][8])

#define W_S_FLOATS   (BBINS * INCH * OUTCH)        // 40960
#define H_S_FLOATS   (BBINS * INCH * HS_STRIDE)    // 10240
#define SMEM_BYTES   ((W_S_FLOATS + H_S_FLOATS) * 4)  // 204800

typedef unsigned long long u64;

__device__ __forceinline__ u64 dup2(float f) {
    u64 r;
    asm("mov.b64 %0, {%1, %1};" : "=l"(r) : "f"(f));
    return r;
}
__device__ __forceinline__ void fma2(u64& d, u64 a, u64 b) {
    // packed 2x fp32 FMA (Blackwell FFMA2)
    asm("fma.rn.f32x2 %0, %1, %2, %0;" : "+l"(d) : "l"(a), "l"(b));
}

__global__ __launch_bounds__(NTHREADS, 1)
void geodesic_fused_kernel(const float* __restrict__ x,
                           const int*   __restrict__ cidx,
                           const float* __restrict__ cval,
                           const float* __restrict__ wts,
                           float*       __restrict__ out)
{
    extern __shared__ float smem[];
    float* W_s = smem;                   // [80][16][32] fp32 = 160 KB
    float* h_s = smem + W_S_FLOATS;      // [1280][8] fp32 (transposed) = 40 KB

    const int tid   = threadIdx.x;
    const int vbase = blockIdx.x * VT;

    // ---- stage all weights into SMEM (coalesced float4 copy) ----
    {
        const float4* src = (const float4*)wts;
        float4*       dst = (float4*)W_s;
        #pragma unroll
        for (int j = 0; j < W_S_FLOATS / 4 / NTHREADS; ++j)   // 40 iters
            dst[tid + j * NTHREADS] = src[tid + j * NTHREADS];
    }

    // ---- gather: build h tile for 8 verts x 80 bins x 16 ch ----
    // 16 threads per conn row: lane c = channel. x row loads are 64B coalesced.
    {
        const int c  = tid & 15;
        const int rg = tid >> 4;        // 0..15 row slot
        #pragma unroll 4
        for (int r0 = 0; r0 < VT * BBINS; r0 += 16) {
            int r = r0 + rg;            // local row 0..639
            int v = r / BBINS;
            int b = r - v * BBINS;
            int grow = (vbase + v) * BBINS + b;      // < 2.4M, fits int
            const int*   ip = cidx + grow * KNNZ;
            const float* vp = cval + grow * KNNZ;
            int   i0 = ip[0], i1 = ip[1], i2 = ip[2];
            float a0 = vp[0], a1 = vp[1], a2 = vp[2];
            float acc = a0 * x[i0 * INCH + c]
                      + a1 * x[i1 * INCH + c]
                      + a2 * x[i2 * INCH + c];
            h_s[(b * INCH + c) * HS_STRIDE + v] = acc;
        }
    }
    __syncthreads();

    // ---- GEMM: thread owns (4 verts, 4 outs, one t) ----
    const int vg = tid >> 7;            // vert group: verts 4*vg .. 4*vg+3
    const int rr = tid & 127;
    const int t  = rr >> 3;             // 0..15
    const int o  = (rr & 7) << 2;       // 0,4,...,28

    u64 acc[2][4];
    #pragma unroll
    for (int a = 0; a < 2; ++a)
        #pragma unroll
        for (int c2 = 0; c2 < 4; ++c2) acc[a][c2] = 0ull;

    int wbin = PBINS * t;               // (b + 5t) % 80, maintained incrementally
    const float* hbase = h_s + vg * 4;

    #pragma unroll 1
    for (int b = 0; b < BBINS; ++b) {
        const float* wp = W_s + wbin * (INCH * OUTCH) + o;
        const float* hp = hbase + b * (INCH * HS_STRIDE);
        #pragma unroll
        for (int i = 0; i < INCH; ++i) {
            // h pair loads: 16B broadcast LDS (same addr for whole warp)
            const ulonglong2 hv = *(const ulonglong2*)(hp + i * HS_STRIDE);
            // weights: 16B per lane, 128B contiguous per t-group -> conflict-free
            const float4 w4 = *(const float4*)(wp + i * OUTCH);
            u64 w0 = dup2(w4.x), w1 = dup2(w4.y), w2 = dup2(w4.z), w3 = dup2(w4.w);
            fma2(acc[0][0], hv.x, w0);
            fma2(acc[0][1], hv.x, w1);
            fma2(acc[0][2], hv.x, w2);
            fma2(acc[0][3], hv.x, w3);
            fma2(acc[1][0], hv.y, w0);
            fma2(acc[1][1], hv.y, w1);
            fma2(acc[1][2], hv.y, w2);
            fma2(acc[1][3], hv.y, w3);
        }
        ++wbin;
        if (wbin == BBINS) wbin = 0;
    }
    __syncthreads();   // everyone done reading h_s before reuse as tmp

    // ---- stage partials tmp[t][vert][o] (reuse h_s region, 16 KB) ----
    float* tmp = h_s;
    #pragma unroll
    for (int vp2 = 0; vp2 < 2; ++vp2) {
        #pragma unroll
        for (int c2 = 0; c2 < 4; ++c2) {
            float lo, hi;
            asm("mov.b64 {%0, %1}, %2;" : "=f"(lo), "=f"(hi) : "l"(acc[vp2][c2]));
            int vlo = vg * 4 + vp2 * 2;
            tmp[(t * VT + vlo    ) * OUTCH + o + c2] = lo;
            tmp[(t * VT + vlo + 1) * OUTCH + o + c2] = hi;
        }
    }
    __syncthreads();

    // ---- max over t, one output per thread (coalesced STG) ----
    {
        int v  = tid >> 5;      // 0..7
        int oo = tid & 31;      // 0..31
        float m = tmp[(0 * VT + v) * OUTCH + oo];
        #pragma unroll
        for (int tt = 1; tt < TBINS; ++tt)
            m = fmaxf(m, tmp[(tt * VT + v) * OUTCH + oo]);
        out[(vbase + v) * OUTCH + oo] = m;
    }
}

extern "C" void kernel_launch(void* const* d_in, const int* in_sizes, int n_in,
                              void* d_out, int out_size)
{
    // metadata order: x (480000 f32), conn_idx (7.2M i32), conn_val (7.2M f32),
    // weights (40960 f32). out: 30000*32 f32.
    const float* x    = (const float*)d_in[0];
    const int*   cidx = (const int*)  d_in[1];
    const float* cval = (const float*)d_in[2];
    const float* wts  = (const float*)d_in[3];
    float* out = (float*)d_out;

    cudaFuncSetAttribute(geodesic_fused_kernel,
                         cudaFuncAttributeMaxDynamicSharedMemorySize, SMEM_BYTES);

    geodesic_fused_kernel<<<NVERT / VT, NTHREADS, SMEM_BYTES>>>(x, cidx, cval, wts, out);
}

// round 3
// speedup vs baseline: 1.0542x; 1.0009x over previous
#include <cuda_runtime.h>

// GeodesicLayer: y[n,o] = max_t sum_{b,i} h[n,b,i] * W[(b+5t)%80][i][o]
// h[n,b,i] = sum_k conn_val[n*80+b,k] * x[conn_idx[n*80+b,k], i]
//
// Constants from the reference:
#define NVERT   30000
#define BBINS   80
#define INCH    16
#define OUTCH   32
#define TBINS   16
#define PBINS   5
#define KNNZ    3

#define VT        8      // vertices per block
#define NTHREADS  256
#define HS_STRIDE 8      // h_s row stride in floats (transposed layout [1280][8])

#define W_S_FLOATS   (BBINS * INCH * OUTCH)        // 40960
#define H_S_FLOATS   (BBINS * INCH * HS_STRIDE)    // 10240
#define SMEM_BYTES   ((W_S_FLOATS + H_S_FLOATS) * 4)  // 204800

typedef unsigned long long u64;

__device__ __forceinline__ u64 dup2(float f) {
    u64 r;
    asm("mov.b64 %0, {%1, %1};" : "=l"(r) : "f"(f));
    return r;
}
__device__ __forceinline__ void fma2(u64& d, u64 a, u64 b) {
    // packed 2x fp32 FMA (Blackwell FFMA2)
    asm("fma.rn.f32x2 %0, %1, %2, %0;" : "+l"(d) : "l"(a), "l"(b));
}

__global__ __launch_bounds__(NTHREADS, 1)
void geodesic_fused_kernel(const float* __restrict__ x,
                           const int*   __restrict__ cidx,
                           const float* __restrict__ cval,
                           const float* __restrict__ wts,
                           float*       __restrict__ out)
{
    extern __shared__ float smem[];
    float* W_s = smem;                   // [80][16][32] fp32 = 160 KB
    float* h_s = smem + W_S_FLOATS;      // [1280][8] fp32 (transposed) = 40 KB

    const int tid   = threadIdx.x;
    const int vbase = blockIdx.x * VT;

    // ---- stage all weights into SMEM (coalesced float4 copy) ----
    {
        const float4* src = (const float4*)wts;
        float4*       dst = (float4*)W_s;
        #pragma unroll
        for (int j = 0; j < W_S_FLOATS / 4 / NTHREADS; ++j)   // 40 iters
            dst[tid + j * NTHREADS] = src[tid + j * NTHREADS];
    }

    // ---- gather: build h tile for 8 verts x 80 bins x 16 ch ----
    // 16 threads per conn row: lane c = channel. x row loads are 64B coalesced.
    {
        const int c  = tid & 15;
        const int rg = tid >> 4;        // 0..15 row slot
        #pragma unroll 4
        for (int r0 = 0; r0 < VT * BBINS; r0 += 16) {
            int r = r0 + rg;            // local row 0..639
            int v = r / BBINS;
            int b = r - v * BBINS;
            int grow = (vbase + v) * BBINS + b;      // < 2.4M, fits int
            const int*   ip = cidx + grow * KNNZ;
            const float* vp = cval + grow * KNNZ;
            int   i0 = ip[0], i1 = ip[1], i2 = ip[2];
            float a0 = vp[0], a1 = vp[1], a2 = vp[2];
            float acc = a0 * x[i0 * INCH + c]
                      + a1 * x[i1 * INCH + c]
                      + a2 * x[i2 * INCH + c];
            h_s[(b * INCH + c) * HS_STRIDE + v] = acc;
        }
    }
    __syncthreads();

    // ---- GEMM: thread owns (4 verts, 4 outs, one t) ----
    const int vg = tid >> 7;            // vert group: verts 4*vg .. 4*vg+3
    const int rr = tid & 127;
    const int t  = rr >> 3;             // 0..15
    const int o  = (rr & 7) << 2;       // 0,4,...,28

    u64 acc[2][4];
    #pragma unroll
    for (int a = 0; a < 2; ++a)
        #pragma unroll
        for (int c2 = 0; c2 < 4; ++c2) acc[a][c2] = 0ull;

    int wbin = PBINS * t;               // (b + 5t) % 80, maintained incrementally
    const float* hbase = h_s + vg * 4;

    #pragma unroll 1
    for (int b = 0; b < BBINS; ++b) {
        const float* wp = W_s + wbin * (INCH * OUTCH) + o;
        const float* hp = hbase + b * (INCH * HS_STRIDE);
        #pragma unroll
        for (int i = 0; i < INCH; ++i) {
            // h pair loads: 16B broadcast LDS (same addr for whole warp)
            const ulonglong2 hv = *(const ulonglong2*)(hp + i * HS_STRIDE);
            // weights: 16B per lane, 128B contiguous per t-group -> conflict-free
            const float4 w4 = *(const float4*)(wp + i * OUTCH);
            u64 w0 = dup2(w4.x), w1 = dup2(w4.y), w2 = dup2(w4.z), w3 = dup2(w4.w);
            fma2(acc[0][0], hv.x, w0);
            fma2(acc[0][1], hv.x, w1);
            fma2(acc[0][2], hv.x, w2);
            fma2(acc[0][3], hv.x, w3);
            fma2(acc[1][0], hv.y, w0);
            fma2(acc[1][1], hv.y, w1);
            fma2(acc[1][2], hv.y, w2);
            fma2(acc[1][3], hv.y, w3);
        }
        ++wbin;
        if (wbin == BBINS) wbin = 0;
    }
    __syncthreads();   // everyone done reading h_s before reuse as tmp

    // ---- stage partials tmp[t][vert][o] (reuse h_s region, 16 KB) ----
    float* tmp = h_s;
    #pragma unroll
    for (int vp2 = 0; vp2 < 2; ++vp2) {
        #pragma unroll
        for (int c2 = 0; c2 < 4; ++c2) {
            float lo, hi;
            asm("mov.b64 {%0, %1}, %2;" : "=f"(lo), "=f"(hi) : "l"(acc[vp2][c2]));
            int vlo = vg * 4 + vp2 * 2;
            tmp[(t * VT + vlo    ) * OUTCH + o + c2] = lo;
            tmp[(t * VT + vlo + 1) * OUTCH + o + c2] = hi;
        }
    }
    __syncthreads();

    // ---- max over t, one output per thread (coalesced STG) ----
    {
        int v  = tid >> 5;      // 0..7
        int oo = tid & 31;      // 0..31
        float m = tmp[(0 * VT + v) * OUTCH + oo];
        #pragma unroll
        for (int tt = 1; tt < TBINS; ++tt)
            m = fmaxf(m, tmp[(tt * VT + v) * OUTCH + oo]);
        out[(vbase + v) * OUTCH + oo] = m;
    }
}

extern "C" void kernel_launch(void* const* d_in, const int* in_sizes, int n_in,
                              void* d_out, int out_size)
{
    // metadata order: x (480000 f32), conn_idx (7.2M i32), conn_val (7.2M f32),
    // weights (40960 f32). out: 30000*32 f32.
    const float* x    = (const float*)d_in[0];
    const int*   cidx = (const int*)  d_in[1];
    const float* cval = (const float*)d_in[2];
    const float* wts  = (const float*)d_in[3];
    float* out = (float*)d_out;

    cudaFuncSetAttribute(geodesic_fused_kernel,
                         cudaFuncAttributeMaxDynamicSharedMemorySize, SMEM_BYTES);

    geodesic_fused_kernel<<<NVERT / VT, NTHREADS, SMEM_BYTES>>>(x, cidx, cval, wts, out);
}